// round 1
// baseline (speedup 1.0000x reference)
#include <cuda_runtime.h>
#include <math.h>

#define NN 50000
#define EE 1600000
#define HD 128
#define GG 512
#define OD 10
#define KIT 10
#define ALPHA_F 0.1f
#define OMA_F 0.9f

// -------- device scratch (no allocations allowed) --------
__device__ float g_x[(size_t)NN * HD];   // ping buffer (also final result)
__device__ float g_y[(size_t)NN * HD];   // pong buffer
__device__ float g_h[(size_t)NN * HD];   // teleport term
__device__ float g_Wc[HD * HD];          // fused W1@W2
__device__ float g_bc[HD];               // fused b1@W2 + b2
__device__ int   g_cnt[NN];              // in-degree histogram
__device__ int   g_rowptr[NN + 1];       // CSR row pointers (by dst)
__device__ int   g_wptr[NN];             // scatter write cursors
__device__ int   g_srcs[EE];             // CSR src indices
__device__ float g_ws[EE];               // CSR edge weights
__device__ float g_pool[GG * HD];        // pooled per-graph features

// ---------------------------------------------------------------------------
// Fuse the two linear layers: Wc = W1 @ W2, bc = b1 @ W2 + b2
// grid = 129 blocks x 128 threads (block 128 computes bc)
// ---------------------------------------------------------------------------
__global__ void fuse_w_k(const float* __restrict__ W1, const float* __restrict__ b1,
                         const float* __restrict__ W2, const float* __restrict__ b2) {
    int h = threadIdx.x;
    if (blockIdx.x < HD) {
        int k = blockIdx.x;
        float s = 0.f;
        #pragma unroll 8
        for (int j = 0; j < HD; j++) s = fmaf(W1[k * HD + j], W2[j * HD + h], s);
        g_Wc[k * HD + h] = s;
    } else {
        float s = b2[h];
        #pragma unroll 8
        for (int j = 0; j < HD; j++) s = fmaf(b1[j], W2[j * HD + h], s);
        g_bc[h] = s;
    }
}

// ---------------------------------------------------------------------------
// x0[n][h] = sum_k F[k][n] * Wc[k][h] + bc[h]; writes both g_x and g_h.
// Tiled fp32 GEMM: block = 128 nodes x 128 dims, 256 threads, 8x8 per thread.
// ---------------------------------------------------------------------------
__global__ __launch_bounds__(256) void gemm_x0_k(const float* __restrict__ F) {
    __shared__ float sF[32][HD + 4];
    __shared__ float sW[32][HD];
    int n0 = blockIdx.x * 128;
    int tx = threadIdx.x & 15;   // dim group
    int ty = threadIdx.x >> 4;   // node group
    float acc[8][8];
    #pragma unroll
    for (int i = 0; i < 8; i++)
        #pragma unroll
        for (int j = 0; j < 8; j++) acc[i][j] = 0.f;

    for (int kt = 0; kt < HD; kt += 32) {
        for (int i = threadIdx.x; i < 32 * 128; i += 256) {
            int kk = i >> 7, c = i & 127;
            int n = n0 + c;
            sF[kk][c] = (n < NN) ? F[(size_t)(kt + kk) * NN + n] : 0.f;
            sW[kk][c] = g_Wc[(kt + kk) * HD + c];
        }
        __syncthreads();
        #pragma unroll
        for (int kk = 0; kk < 32; kk++) {
            float a[8], b[8];
            #pragma unroll
            for (int i = 0; i < 8; i++) a[i] = sF[kk][ty * 8 + i];
            #pragma unroll
            for (int j = 0; j < 8; j++) b[j] = sW[kk][tx * 8 + j];
            #pragma unroll
            for (int i = 0; i < 8; i++)
                #pragma unroll
                for (int j = 0; j < 8; j++) acc[i][j] = fmaf(a[i], b[j], acc[i][j]);
        }
        __syncthreads();
    }
    #pragma unroll
    for (int i = 0; i < 8; i++) {
        int n = n0 + ty * 8 + i;
        if (n < NN) {
            #pragma unroll
            for (int j = 0; j < 8; j++) {
                int hcol = tx * 8 + j;
                float v = acc[i][j] + g_bc[hcol];
                g_x[(size_t)n * HD + hcol] = v;
                g_h[(size_t)n * HD + hcol] = v;
            }
        }
    }
}

// ---------------------------------------------------------------------------
// Zero histogram + pool buffer
// ---------------------------------------------------------------------------
__global__ void zero_k() {
    int i = blockIdx.x * blockDim.x + threadIdx.x;
    if (i < NN) g_cnt[i] = 0;
    if (i < GG * HD) g_pool[i] = 0.f;
}

// ---------------------------------------------------------------------------
// In-degree histogram over dst
// ---------------------------------------------------------------------------
__global__ void hist_k(const int* __restrict__ ei) {
    int e = blockIdx.x * blockDim.x + threadIdx.x;
    if (e < EE) atomicAdd(&g_cnt[ei[EE + e]], 1);
}

// ---------------------------------------------------------------------------
// Exclusive scan of g_cnt -> g_rowptr (and g_wptr = exclusive cursors).
// Single block, 1024 threads, Hillis-Steele per 1024-chunk with carry.
// ---------------------------------------------------------------------------
__global__ __launch_bounds__(1024) void scan_k() {
    __shared__ int sh[1024];
    __shared__ int carry_sh;
    int t = threadIdx.x;
    if (t == 0) { carry_sh = 0; g_rowptr[0] = 0; }
    __syncthreads();
    for (int base = 0; base < NN; base += 1024) {
        int idx = base + t;
        int c = (idx < NN) ? g_cnt[idx] : 0;
        sh[t] = c;
        __syncthreads();
        #pragma unroll
        for (int off = 1; off < 1024; off <<= 1) {
            int v = (t >= off) ? sh[t - off] : 0;
            __syncthreads();
            sh[t] += v;
            __syncthreads();
        }
        int incl = sh[t];
        int carry = carry_sh;
        if (idx < NN) {
            g_rowptr[idx + 1] = carry + incl;
            g_wptr[idx]       = carry + incl - c;
        }
        __syncthreads();
        if (t == 1023) carry_sh = carry + incl;
        __syncthreads();
    }
}

// ---------------------------------------------------------------------------
// Scatter edges into CSR order (by dst)
// ---------------------------------------------------------------------------
__global__ void scatter_k(const int* __restrict__ ei, const float* __restrict__ ew) {
    int e = blockIdx.x * blockDim.x + threadIdx.x;
    if (e < EE) {
        int d = ei[EE + e];
        int pos = atomicAdd(&g_wptr[d], 1);
        g_srcs[pos] = ei[e];
        g_ws[pos]   = ew[e];
    }
}

// ---------------------------------------------------------------------------
// One APPNP step: xout[d] = 0.9 * sum_{e: dst=d} w_e * xin[src_e] + 0.1 * h[d]
// One warp per dst node; 32 lanes x float4 = 128 dims.
// flip==0: g_x -> g_y ; flip==1: g_y -> g_x
// ---------------------------------------------------------------------------
__global__ __launch_bounds__(256) void prop_k(int flip) {
    const float* __restrict__ xin  = flip ? g_y : g_x;
    float* __restrict__       xout = flip ? g_x : g_y;
    int warp_id = (blockIdx.x * blockDim.x + threadIdx.x) >> 5;
    int lane = threadIdx.x & 31;
    if (warp_id >= NN) return;
    int node = warp_id;
    int beg = g_rowptr[node];
    int end = g_rowptr[node + 1];
    float4 acc = make_float4(0.f, 0.f, 0.f, 0.f);
    for (int j = beg; j < end; j += 32) {
        int me = j + lane;
        int s = 0; float w = 0.f;
        if (me < end) { s = g_srcs[me]; w = g_ws[me]; }
        int cnt = min(32, end - j);
        #pragma unroll 4
        for (int t = 0; t < cnt; t++) {
            int   ss = __shfl_sync(0xffffffffu, s, t);
            float ww = __shfl_sync(0xffffffffu, w, t);
            float4 v = reinterpret_cast<const float4*>(xin + (size_t)ss * HD)[lane];
            acc.x = fmaf(ww, v.x, acc.x);
            acc.y = fmaf(ww, v.y, acc.y);
            acc.z = fmaf(ww, v.z, acc.z);
            acc.w = fmaf(ww, v.w, acc.w);
        }
    }
    float4 hv = reinterpret_cast<const float4*>(g_h + (size_t)node * HD)[lane];
    float4 o;
    o.x = OMA_F * acc.x + ALPHA_F * hv.x;
    o.y = OMA_F * acc.y + ALPHA_F * hv.y;
    o.z = OMA_F * acc.z + ALPHA_F * hv.z;
    o.w = OMA_F * acc.w + ALPHA_F * hv.w;
    reinterpret_cast<float4*>(xout + (size_t)node * HD)[lane] = o;
}

// ---------------------------------------------------------------------------
// Segment-sum pooling over sorted batch. One warp per 64-node chunk with
// warp-local accumulation; flush atomically on segment boundary.
// Reads final x from g_x.
// ---------------------------------------------------------------------------
__device__ __forceinline__ void pool_flush(int g, float4 acc, int lane) {
    float* p = g_pool + (size_t)g * HD + lane * 4;
    atomicAdd(p + 0, acc.x);
    atomicAdd(p + 1, acc.y);
    atomicAdd(p + 2, acc.z);
    atomicAdd(p + 3, acc.w);
}

__global__ __launch_bounds__(256) void pool_k(const int* __restrict__ batch) {
    int warp_id = (blockIdx.x * blockDim.x + threadIdx.x) >> 5;
    int lane = threadIdx.x & 31;
    int n0 = warp_id * 64;
    if (n0 >= NN) return;
    int n1 = min(n0 + 64, NN);
    float4 acc = make_float4(0.f, 0.f, 0.f, 0.f);
    int curg = batch[n0];
    for (int n = n0; n < n1; n++) {
        int g = batch[n];
        if (g != curg) {
            pool_flush(curg, acc, lane);
            acc = make_float4(0.f, 0.f, 0.f, 0.f);
            curg = g;
        }
        float4 v = reinterpret_cast<const float4*>(g_x + (size_t)n * HD)[lane];
        acc.x += v.x; acc.y += v.y; acc.z += v.z; acc.w += v.w;
    }
    pool_flush(curg, acc, lane);
}

// ---------------------------------------------------------------------------
// Head: y = relu(pool @ V0w + V0b) @ V1w + V1b; out = log_softmax(y)
// One block per graph, 128 threads.
// ---------------------------------------------------------------------------
__global__ __launch_bounds__(128) void head_k(const float* __restrict__ V0w,
                                              const float* __restrict__ V0b,
                                              const float* __restrict__ V1w,
                                              const float* __restrict__ V1b,
                                              float* __restrict__ out) {
    __shared__ float sp[HD];
    __shared__ float sz[HD];
    __shared__ float sy[OD];
    int g = blockIdx.x;
    int t = threadIdx.x;
    sp[t] = g_pool[(size_t)g * HD + t];
    __syncthreads();
    float s = V0b[t];
    #pragma unroll 8
    for (int k = 0; k < HD; k++) s = fmaf(sp[k], V0w[k * HD + t], s);
    sz[t] = fmaxf(s, 0.f);
    __syncthreads();
    if (t < OD) {
        float y = V1b[t];
        #pragma unroll 8
        for (int h = 0; h < HD; h++) y = fmaf(sz[h], V1w[h * OD + t], y);
        sy[t] = y;
    }
    __syncthreads();
    if (t == 0) {
        float m = -INFINITY;
        #pragma unroll
        for (int o = 0; o < OD; o++) m = fmaxf(m, sy[o]);
        float sum = 0.f;
        #pragma unroll
        for (int o = 0; o < OD; o++) sum += expf(sy[o] - m);
        float lse = m + logf(sum);
        #pragma unroll
        for (int o = 0; o < OD; o++) out[g * OD + o] = sy[o] - lse;
    }
}

// ---------------------------------------------------------------------------
extern "C" void kernel_launch(void* const* d_in, const int* in_sizes, int n_in,
                              void* d_out, int out_size) {
    const float* features    = (const float*)d_in[0];
    const float* edge_weight = (const float*)d_in[1];
    const float* W1  = (const float*)d_in[2];
    const float* b1  = (const float*)d_in[3];
    const float* W2  = (const float*)d_in[4];
    const float* b2  = (const float*)d_in[5];
    const float* V0w = (const float*)d_in[6];
    const float* V0b = (const float*)d_in[7];
    const float* V1w = (const float*)d_in[8];
    const float* V1b = (const float*)d_in[9];
    const int* edge_index = (const int*)d_in[10];
    const int* batch      = (const int*)d_in[11];
    float* out = (float*)d_out;

    // MLP front (fused)
    fuse_w_k<<<HD + 1, HD>>>(W1, b1, W2, b2);
    gemm_x0_k<<<(NN + 127) / 128, 256>>>(features);

    // CSR build (by dst)
    zero_k<<<(GG * HD + 255) / 256, 256>>>();
    hist_k<<<(EE + 255) / 256, 256>>>(edge_index);
    scan_k<<<1, 1024>>>();
    scatter_k<<<(EE + 255) / 256, 256>>>(edge_index, edge_weight);

    // APPNP propagation, K=10 (ends in g_x)
    int prop_blocks = (NN * 32 + 255) / 256;
    for (int it = 0; it < KIT; it++) {
        prop_k<<<prop_blocks, 256>>>(it & 1);
    }

    // Pool + head
    int pool_warps = (NN + 63) / 64;
    pool_k<<<(pool_warps * 32 + 255) / 256, 256>>>(batch);
    head_k<<<GG, HD>>>(V0w, V0b, V1w, V1b, out);
}

// round 4
// speedup vs baseline: 1.3850x; 1.3850x over previous
#include <cuda_runtime.h>
#include <cuda_fp16.h>
#include <math.h>

#define NN 50000
#define EE 1600000
#define HD 128
#define GG 512
#define OD 10
#define KIT 10
#define ALPHA_F 0.1f
#define COEF_A (0.9f / 16.0f)        // per-step rescale by 16
#define FINAL_SCALE 1099511627776.0f // 16^10 = 2^40 (exact)

// -------- device scratch (no allocations allowed) --------
__device__ __half g_u0[(size_t)NN * HD];   // ping (scaled x)
__device__ __half g_u1[(size_t)NN * HD];   // pong
__device__ float  g_h[(size_t)NN * HD];    // teleport term (fp32 for accuracy)
__device__ float  g_Wc[HD * HD];           // fused W1@W2
__device__ float  g_bc[HD];                // fused b1@W2 + b2
__device__ int    g_cnt[NN];               // in-degree histogram
__device__ int    g_rowptr[NN + 1];        // CSR row pointers (by dst)
__device__ int    g_wptr[NN];              // scatter write cursors
__device__ unsigned short g_srcs[EE];      // CSR src indices (N < 65536)
__device__ float  g_ws[EE];                // CSR edge weights
__device__ float  g_pool[GG * HD];         // pooled per-graph features

// ---------------------------------------------------------------------------
// Fuse the two linear layers: Wc = W1 @ W2, bc = b1 @ W2 + b2
// ---------------------------------------------------------------------------
__global__ void fuse_w_k(const float* __restrict__ W1, const float* __restrict__ b1,
                         const float* __restrict__ W2, const float* __restrict__ b2) {
    int h = threadIdx.x;
    if (blockIdx.x < HD) {
        int k = blockIdx.x;
        float s = 0.f;
        #pragma unroll 8
        for (int j = 0; j < HD; j++) s = fmaf(W1[k * HD + j], W2[j * HD + h], s);
        g_Wc[k * HD + h] = s;
    } else {
        float s = b2[h];
        #pragma unroll 8
        for (int j = 0; j < HD; j++) s = fmaf(b1[j], W2[j * HD + h], s);
        g_bc[h] = s;
    }
}

// ---------------------------------------------------------------------------
// x0[n][h] = sum_k F[k][n] * Wc[k][h] + bc[h]; writes g_u0 (fp16) and g_h (fp32).
// Tiled fp32 GEMM: block = 128 nodes x 128 dims, 256 threads, 8x8 per thread.
// ---------------------------------------------------------------------------
__global__ __launch_bounds__(256) void gemm_x0_k(const float* __restrict__ F) {
    __shared__ float sF[32][HD + 4];
    __shared__ float sW[32][HD];
    int n0 = blockIdx.x * 128;
    int tx = threadIdx.x & 15;   // dim group
    int ty = threadIdx.x >> 4;   // node group
    float acc[8][8];
    #pragma unroll
    for (int i = 0; i < 8; i++)
        #pragma unroll
        for (int j = 0; j < 8; j++) acc[i][j] = 0.f;

    for (int kt = 0; kt < HD; kt += 32) {
        for (int i = threadIdx.x; i < 32 * 128; i += 256) {
            int kk = i >> 7, c = i & 127;
            int n = n0 + c;
            sF[kk][c] = (n < NN) ? F[(size_t)(kt + kk) * NN + n] : 0.f;
            sW[kk][c] = g_Wc[(kt + kk) * HD + c];
        }
        __syncthreads();
        #pragma unroll
        for (int kk = 0; kk < 32; kk++) {
            float a[8], b[8];
            #pragma unroll
            for (int i = 0; i < 8; i++) a[i] = sF[kk][ty * 8 + i];
            #pragma unroll
            for (int j = 0; j < 8; j++) b[j] = sW[kk][tx * 8 + j];
            #pragma unroll
            for (int i = 0; i < 8; i++)
                #pragma unroll
                for (int j = 0; j < 8; j++) acc[i][j] = fmaf(a[i], b[j], acc[i][j]);
        }
        __syncthreads();
    }
    #pragma unroll
    for (int i = 0; i < 8; i++) {
        int n = n0 + ty * 8 + i;
        if (n < NN) {
            __align__(16) __half hb[8];
            #pragma unroll
            for (int j = 0; j < 8; j++) {
                float v = acc[i][j] + g_bc[tx * 8 + j];
                g_h[(size_t)n * HD + tx * 8 + j] = v;
                hb[j] = __float2half_rn(v);
            }
            *reinterpret_cast<uint4*>(&g_u0[(size_t)n * HD + tx * 8]) =
                *reinterpret_cast<uint4*>(hb);
        }
    }
}

// ---------------------------------------------------------------------------
// Zero histogram + pool buffer
// ---------------------------------------------------------------------------
__global__ void zero_k() {
    int i = blockIdx.x * blockDim.x + threadIdx.x;
    if (i < NN) g_cnt[i] = 0;
    if (i < GG * HD) g_pool[i] = 0.f;
}

// ---------------------------------------------------------------------------
// In-degree histogram over dst
// ---------------------------------------------------------------------------
__global__ void hist_k(const int* __restrict__ ei) {
    int e = blockIdx.x * blockDim.x + threadIdx.x;
    if (e < EE) atomicAdd(&g_cnt[ei[EE + e]], 1);
}

// ---------------------------------------------------------------------------
// Exclusive scan of g_cnt -> g_rowptr / g_wptr. Single block, 1024 threads,
// warp-shuffle scan.
// ---------------------------------------------------------------------------
__global__ __launch_bounds__(1024) void scan_k() {
    __shared__ int wsum[32];
    __shared__ int carry_sh;
    int t = threadIdx.x;
    int lane = t & 31;
    int wid = t >> 5;
    if (t == 0) { carry_sh = 0; g_rowptr[0] = 0; }
    __syncthreads();
    for (int base = 0; base < NN; base += 1024) {
        int idx = base + t;
        int c = (idx < NN) ? g_cnt[idx] : 0;
        int v = c;
        #pragma unroll
        for (int off = 1; off < 32; off <<= 1) {
            int u = __shfl_up_sync(0xffffffffu, v, off);
            if (lane >= off) v += u;
        }
        if (lane == 31) wsum[wid] = v;
        __syncthreads();
        if (wid == 0) {
            int s = wsum[lane];
            #pragma unroll
            for (int off = 1; off < 32; off <<= 1) {
                int u = __shfl_up_sync(0xffffffffu, s, off);
                if (lane >= off) s += u;
            }
            wsum[lane] = s;
        }
        __syncthreads();
        int incl = v + (wid ? wsum[wid - 1] : 0);
        int chunk_total = wsum[31];
        int carry = carry_sh;
        if (idx < NN) {
            g_rowptr[idx + 1] = carry + incl;
            g_wptr[idx]       = carry + incl - c;
        }
        __syncthreads();
        if (t == 0) carry_sh = carry + chunk_total;
        __syncthreads();
    }
}

// ---------------------------------------------------------------------------
// Scatter edges into CSR order (by dst); src packed to u16
// ---------------------------------------------------------------------------
__global__ void scatter_k(const int* __restrict__ ei, const float* __restrict__ ew) {
    int e = blockIdx.x * blockDim.x + threadIdx.x;
    if (e < EE) {
        int d = ei[EE + e];
        int pos = atomicAdd(&g_wptr[d], 1);
        g_srcs[pos] = (unsigned short)ei[e];
        g_ws[pos]   = ew[e];
    }
}

// ---------------------------------------------------------------------------
// One scaled APPNP step:
//   u_out[d] = (0.9/16) * sum_e w_e * u_in[src_e] + (0.1/16^{k+1}) * h[d]
// One warp per dst node; lane covers 4 dims (8B fp16), fp32 accumulation.
// ---------------------------------------------------------------------------
__global__ __launch_bounds__(256) void prop_k(int flip, float coefH) {
    const __half* __restrict__ xin  = flip ? g_u1 : g_u0;
    __half* __restrict__       xout = flip ? g_u0 : g_u1;
    int warp_id = (blockIdx.x * blockDim.x + threadIdx.x) >> 5;
    int lane = threadIdx.x & 31;
    if (warp_id >= NN) return;
    int node = warp_id;
    int beg = g_rowptr[node];
    int end = g_rowptr[node + 1];
    float4 acc = make_float4(0.f, 0.f, 0.f, 0.f);
    for (int j = beg; j < end; j += 32) {
        int me = j + lane;
        int s = 0; float w = 0.f;
        if (me < end) { s = (int)g_srcs[me]; w = g_ws[me]; }
        int cnt = min(32, end - j);
        #pragma unroll 4
        for (int t = 0; t < cnt; t++) {
            int   ss = __shfl_sync(0xffffffffu, s, t);
            float ww = __shfl_sync(0xffffffffu, w, t);
            uint2 raw = *reinterpret_cast<const uint2*>(xin + (size_t)ss * HD + lane * 4);
            float2 fa = __half22float2(*reinterpret_cast<const __half2*>(&raw.x));
            float2 fb = __half22float2(*reinterpret_cast<const __half2*>(&raw.y));
            acc.x = fmaf(ww, fa.x, acc.x);
            acc.y = fmaf(ww, fa.y, acc.y);
            acc.z = fmaf(ww, fb.x, acc.z);
            acc.w = fmaf(ww, fb.y, acc.w);
        }
    }
    float4 hv = *reinterpret_cast<const float4*>(g_h + (size_t)node * HD + lane * 4);
    __align__(8) __half ob[4];
    ob[0] = __float2half_rn(fmaf(COEF_A, acc.x, coefH * hv.x));
    ob[1] = __float2half_rn(fmaf(COEF_A, acc.y, coefH * hv.y));
    ob[2] = __float2half_rn(fmaf(COEF_A, acc.z, coefH * hv.z));
    ob[3] = __float2half_rn(fmaf(COEF_A, acc.w, coefH * hv.w));
    *reinterpret_cast<uint2*>(xout + (size_t)node * HD + lane * 4) =
        *reinterpret_cast<uint2*>(ob);
}

// ---------------------------------------------------------------------------
// Segment-sum pooling over sorted batch (reads final u from g_u0, unscales
// by 16^10 = 2^40).
// ---------------------------------------------------------------------------
__device__ __forceinline__ void pool_flush(int g, float4 acc, int lane) {
    float* p = g_pool + (size_t)g * HD + lane * 4;
    atomicAdd(p + 0, acc.x * FINAL_SCALE);
    atomicAdd(p + 1, acc.y * FINAL_SCALE);
    atomicAdd(p + 2, acc.z * FINAL_SCALE);
    atomicAdd(p + 3, acc.w * FINAL_SCALE);
}

__global__ __launch_bounds__(256) void pool_k(const int* __restrict__ batch) {
    int warp_id = (blockIdx.x * blockDim.x + threadIdx.x) >> 5;
    int lane = threadIdx.x & 31;
    int n0 = warp_id * 64;
    if (n0 >= NN) return;
    int n1 = min(n0 + 64, NN);
    float4 acc = make_float4(0.f, 0.f, 0.f, 0.f);
    int curg = batch[n0];
    for (int n = n0; n < n1; n++) {
        int g = batch[n];
        if (g != curg) {
            pool_flush(curg, acc, lane);
            acc = make_float4(0.f, 0.f, 0.f, 0.f);
            curg = g;
        }
        uint2 raw = *reinterpret_cast<const uint2*>(g_u0 + (size_t)n * HD + lane * 4);
        float2 fa = __half22float2(*reinterpret_cast<const __half2*>(&raw.x));
        float2 fb = __half22float2(*reinterpret_cast<const __half2*>(&raw.y));
        acc.x += fa.x; acc.y += fa.y; acc.z += fb.x; acc.w += fb.y;
    }
    pool_flush(curg, acc, lane);
}

// ---------------------------------------------------------------------------
// Head: y = relu(pool @ V0w + V0b) @ V1w + V1b; out = log_softmax(y)
// ---------------------------------------------------------------------------
__global__ __launch_bounds__(128) void head_k(const float* __restrict__ V0w,
                                              const float* __restrict__ V0b,
                                              const float* __restrict__ V1w,
                                              const float* __restrict__ V1b,
                                              float* __restrict__ out) {
    __shared__ float sp[HD];
    __shared__ float sz[HD];
    __shared__ float sy[OD];
    int g = blockIdx.x;
    int t = threadIdx.x;
    sp[t] = g_pool[(size_t)g * HD + t];
    __syncthreads();
    float s = V0b[t];
    #pragma unroll 8
    for (int k = 0; k < HD; k++) s = fmaf(sp[k], V0w[k * HD + t], s);
    sz[t] = fmaxf(s, 0.f);
    __syncthreads();
    if (t < OD) {
        float y = V1b[t];
        #pragma unroll 8
        for (int h = 0; h < HD; h++) y = fmaf(sz[h], V1w[h * OD + t], y);
        sy[t] = y;
    }
    __syncthreads();
    if (t == 0) {
        float m = -INFINITY;
        #pragma unroll
        for (int o = 0; o < OD; o++) m = fmaxf(m, sy[o]);
        float sum = 0.f;
        #pragma unroll
        for (int o = 0; o < OD; o++) sum += expf(sy[o] - m);
        float lse = m + logf(sum);
        #pragma unroll
        for (int o = 0; o < OD; o++) out[g * OD + o] = sy[o] - lse;
    }
}

// ---------------------------------------------------------------------------
extern "C" void kernel_launch(void* const* d_in, const int* in_sizes, int n_in,
                              void* d_out, int out_size) {
    const float* features    = (const float*)d_in[0];
    const float* edge_weight = (const float*)d_in[1];
    const float* W1  = (const float*)d_in[2];
    const float* b1  = (const float*)d_in[3];
    const float* W2  = (const float*)d_in[4];
    const float* b2  = (const float*)d_in[5];
    const float* V0w = (const float*)d_in[6];
    const float* V0b = (const float*)d_in[7];
    const float* V1w = (const float*)d_in[8];
    const float* V1b = (const float*)d_in[9];
    const int* edge_index = (const int*)d_in[10];
    const int* batch      = (const int*)d_in[11];
    float* out = (float*)d_out;

    // MLP front (fused)
    fuse_w_k<<<HD + 1, HD>>>(W1, b1, W2, b2);
    gemm_x0_k<<<(NN + 127) / 128, 256>>>(features);

    // CSR build (by dst)
    zero_k<<<(GG * HD + 255) / 256, 256>>>();
    hist_k<<<(EE + 255) / 256, 256>>>(edge_index);
    scan_k<<<1, 1024>>>();
    scatter_k<<<(EE + 255) / 256, 256>>>(edge_index, edge_weight);

    // APPNP propagation, K=10 (scaled fp16; ends in g_u0)
    int prop_blocks = (NN * 32 + 255) / 256;
    float cscale = 1.0f;   // 1/16^{it}
    for (int it = 0; it < KIT; it++) {
        cscale *= 0.0625f;                    // 1/16^{it+1}
        float coefH = ALPHA_F * cscale;
        prop_k<<<prop_blocks, 256>>>(it & 1, coefH);
    }

    // Pool + head
    int pool_warps = (NN + 63) / 64;
    pool_k<<<(pool_warps * 32 + 255) / 256, 256>>>(batch);
    head_k<<<GG, HD>>>(V0w, V0b, V1w, V1b, out);
}

// round 5
// speedup vs baseline: 1.5188x; 1.0966x over previous
#include <cuda_runtime.h>
#include <cuda_fp16.h>
#include <math.h>

#define NN 50000
#define EE 1600000
#define HD 128
#define GG 512
#define OD 10
#define KIT 10
#define ALPHA_F 0.1f
#define COEF_A (0.9f / 16.0f)        // per-step rescale by 16
#define FINAL_SCALE 1099511627776.0f // 16^10 = 2^40 (exact)

// -------- device scratch (no allocations allowed) --------
__device__ __half g_u0[(size_t)NN * HD];   // ping (scaled x)
__device__ __half g_u1[(size_t)NN * HD];   // pong
__device__ __half g_hh[(size_t)NN * HD];   // teleport term (fp16)
__device__ float  g_Wc[HD * HD];           // fused W1@W2
__device__ float  g_bc[HD];                // fused b1@W2 + b2
__device__ int    g_cnt[NN];               // in-degree histogram
__device__ int    g_rowptr[NN + 1];        // CSR row pointers (by dst)
__device__ int    g_wptr[NN];              // scatter write cursors
__device__ unsigned int g_edges[EE];       // packed: (half w)<<16 | u16 src
__device__ float  g_pool[GG * HD];         // pooled per-graph features

// ---------------------------------------------------------------------------
// Fuse the two linear layers: Wc = W1 @ W2, bc = b1 @ W2 + b2
// ---------------------------------------------------------------------------
__global__ void fuse_w_k(const float* __restrict__ W1, const float* __restrict__ b1,
                         const float* __restrict__ W2, const float* __restrict__ b2) {
    int h = threadIdx.x;
    if (blockIdx.x < HD) {
        int k = blockIdx.x;
        float s = 0.f;
        #pragma unroll 8
        for (int j = 0; j < HD; j++) s = fmaf(W1[k * HD + j], W2[j * HD + h], s);
        g_Wc[k * HD + h] = s;
    } else {
        float s = b2[h];
        #pragma unroll 8
        for (int j = 0; j < HD; j++) s = fmaf(b1[j], W2[j * HD + h], s);
        g_bc[h] = s;
    }
}

// ---------------------------------------------------------------------------
// x0[n][h] = sum_k F[k][n] * Wc[k][h] + bc[h]; writes g_u0 and g_hh (fp16).
// Tiled fp32 GEMM: block = 128 nodes x 128 dims, 256 threads, 8x8 per thread.
// ---------------------------------------------------------------------------
__global__ __launch_bounds__(256) void gemm_x0_k(const float* __restrict__ F) {
    __shared__ float sF[32][HD + 4];
    __shared__ float sW[32][HD];
    int n0 = blockIdx.x * 128;
    int tx = threadIdx.x & 15;   // dim group
    int ty = threadIdx.x >> 4;   // node group
    float acc[8][8];
    #pragma unroll
    for (int i = 0; i < 8; i++)
        #pragma unroll
        for (int j = 0; j < 8; j++) acc[i][j] = 0.f;

    for (int kt = 0; kt < HD; kt += 32) {
        for (int i = threadIdx.x; i < 32 * 128; i += 256) {
            int kk = i >> 7, c = i & 127;
            int n = n0 + c;
            sF[kk][c] = (n < NN) ? F[(size_t)(kt + kk) * NN + n] : 0.f;
            sW[kk][c] = g_Wc[(kt + kk) * HD + c];
        }
        __syncthreads();
        #pragma unroll
        for (int kk = 0; kk < 32; kk++) {
            float a[8], b[8];
            #pragma unroll
            for (int i = 0; i < 8; i++) a[i] = sF[kk][ty * 8 + i];
            #pragma unroll
            for (int j = 0; j < 8; j++) b[j] = sW[kk][tx * 8 + j];
            #pragma unroll
            for (int i = 0; i < 8; i++)
                #pragma unroll
                for (int j = 0; j < 8; j++) acc[i][j] = fmaf(a[i], b[j], acc[i][j]);
        }
        __syncthreads();
    }
    #pragma unroll
    for (int i = 0; i < 8; i++) {
        int n = n0 + ty * 8 + i;
        if (n < NN) {
            __align__(16) __half hb[8];
            #pragma unroll
            for (int j = 0; j < 8; j++) {
                float v = acc[i][j] + g_bc[tx * 8 + j];
                hb[j] = __float2half_rn(v);
            }
            uint4 pk = *reinterpret_cast<uint4*>(hb);
            *reinterpret_cast<uint4*>(&g_u0[(size_t)n * HD + tx * 8]) = pk;
            *reinterpret_cast<uint4*>(&g_hh[(size_t)n * HD + tx * 8]) = pk;
        }
    }
}

// ---------------------------------------------------------------------------
// Zero histogram + pool buffer
// ---------------------------------------------------------------------------
__global__ void zero_k() {
    int i = blockIdx.x * blockDim.x + threadIdx.x;
    if (i < NN) g_cnt[i] = 0;
    if (i < GG * HD) g_pool[i] = 0.f;
}

// ---------------------------------------------------------------------------
// In-degree histogram over dst
// ---------------------------------------------------------------------------
__global__ void hist_k(const int* __restrict__ ei) {
    int e = blockIdx.x * blockDim.x + threadIdx.x;
    if (e < EE) atomicAdd(&g_cnt[ei[EE + e]], 1);
}

// ---------------------------------------------------------------------------
// Exclusive scan of g_cnt -> g_rowptr / g_wptr. Single block, 1024 threads,
// warp-shuffle scan.
// ---------------------------------------------------------------------------
__global__ __launch_bounds__(1024) void scan_k() {
    __shared__ int wsum[32];
    __shared__ int carry_sh;
    int t = threadIdx.x;
    int lane = t & 31;
    int wid = t >> 5;
    if (t == 0) { carry_sh = 0; g_rowptr[0] = 0; }
    __syncthreads();
    for (int base = 0; base < NN; base += 1024) {
        int idx = base + t;
        int c = (idx < NN) ? g_cnt[idx] : 0;
        int v = c;
        #pragma unroll
        for (int off = 1; off < 32; off <<= 1) {
            int u = __shfl_up_sync(0xffffffffu, v, off);
            if (lane >= off) v += u;
        }
        if (lane == 31) wsum[wid] = v;
        __syncthreads();
        if (wid == 0) {
            int s = wsum[lane];
            #pragma unroll
            for (int off = 1; off < 32; off <<= 1) {
                int u = __shfl_up_sync(0xffffffffu, s, off);
                if (lane >= off) s += u;
            }
            wsum[lane] = s;
        }
        __syncthreads();
        int incl = v + (wid ? wsum[wid - 1] : 0);
        int chunk_total = wsum[31];
        int carry = carry_sh;
        if (idx < NN) {
            g_rowptr[idx + 1] = carry + incl;
            g_wptr[idx]       = carry + incl - c;
        }
        __syncthreads();
        if (t == 0) carry_sh = carry + chunk_total;
        __syncthreads();
    }
}

// ---------------------------------------------------------------------------
// Scatter edges into CSR order (by dst); packed record (half w)<<16 | u16 src
// ---------------------------------------------------------------------------
__global__ void scatter_k(const int* __restrict__ ei, const float* __restrict__ ew) {
    int e = blockIdx.x * blockDim.x + threadIdx.x;
    if (e < EE) {
        int d = ei[EE + e];
        int pos = atomicAdd(&g_wptr[d], 1);
        unsigned short wb = __half_as_ushort(__float2half_rn(ew[e]));
        g_edges[pos] = ((unsigned int)wb << 16) | (unsigned int)(ei[e] & 0xFFFF);
    }
}

// ---------------------------------------------------------------------------
// One scaled APPNP step:
//   u_out[d] = (0.9/16) * sum_e w_e * u_in[src_e] + (0.1/16^{k+1}) * h[d]
// HALF-WARP per dst node: 16 lanes x uint4(16B) cover the 256B fp16 row.
// Edge records broadcast-loaded (uniform address within the half-warp).
// ---------------------------------------------------------------------------
__global__ __launch_bounds__(256) void prop_k(int flip, float coefH) {
    const uint4* __restrict__ xin =
        reinterpret_cast<const uint4*>(flip ? g_u1 : g_u0);
    uint4* __restrict__ xout =
        reinterpret_cast<uint4*>(flip ? g_u0 : g_u1);
    int node = (blockIdx.x * blockDim.x + threadIdx.x) >> 4;  // half-warp id
    int sub = threadIdx.x & 15;
    if (node >= NN) return;
    int beg = g_rowptr[node];
    int end = g_rowptr[node + 1];
    float2 a0 = make_float2(0.f, 0.f), a1 = a0, a2 = a0, a3 = a0;
    #pragma unroll 2
    for (int j = beg; j < end; j++) {
        unsigned int rec = g_edges[j];            // broadcast within half-warp
        int src = (int)(rec & 0xFFFFu);
        float w = __half2float(__ushort_as_half((unsigned short)(rec >> 16)));
        uint4 raw = xin[src * 16 + sub];          // 16B of the 256B row
        float2 p0 = __half22float2(*reinterpret_cast<const __half2*>(&raw.x));
        float2 p1 = __half22float2(*reinterpret_cast<const __half2*>(&raw.y));
        float2 p2 = __half22float2(*reinterpret_cast<const __half2*>(&raw.z));
        float2 p3 = __half22float2(*reinterpret_cast<const __half2*>(&raw.w));
        a0.x = fmaf(w, p0.x, a0.x); a0.y = fmaf(w, p0.y, a0.y);
        a1.x = fmaf(w, p1.x, a1.x); a1.y = fmaf(w, p1.y, a1.y);
        a2.x = fmaf(w, p2.x, a2.x); a2.y = fmaf(w, p2.y, a2.y);
        a3.x = fmaf(w, p3.x, a3.x); a3.y = fmaf(w, p3.y, a3.y);
    }
    uint4 hraw = reinterpret_cast<const uint4*>(g_hh)[node * 16 + sub];
    float2 h0 = __half22float2(*reinterpret_cast<const __half2*>(&hraw.x));
    float2 h1 = __half22float2(*reinterpret_cast<const __half2*>(&hraw.y));
    float2 h2 = __half22float2(*reinterpret_cast<const __half2*>(&hraw.z));
    float2 h3 = __half22float2(*reinterpret_cast<const __half2*>(&hraw.w));
    float2 o0, o1, o2, o3;
    o0.x = fmaf(COEF_A, a0.x, coefH * h0.x); o0.y = fmaf(COEF_A, a0.y, coefH * h0.y);
    o1.x = fmaf(COEF_A, a1.x, coefH * h1.x); o1.y = fmaf(COEF_A, a1.y, coefH * h1.y);
    o2.x = fmaf(COEF_A, a2.x, coefH * h2.x); o2.y = fmaf(COEF_A, a2.y, coefH * h2.y);
    o3.x = fmaf(COEF_A, a3.x, coefH * h3.x); o3.y = fmaf(COEF_A, a3.y, coefH * h3.y);
    uint4 outw;
    *reinterpret_cast<__half2*>(&outw.x) = __float22half2_rn(o0);
    *reinterpret_cast<__half2*>(&outw.y) = __float22half2_rn(o1);
    *reinterpret_cast<__half2*>(&outw.z) = __float22half2_rn(o2);
    *reinterpret_cast<__half2*>(&outw.w) = __float22half2_rn(o3);
    xout[node * 16 + sub] = outw;
}

// ---------------------------------------------------------------------------
// Segment-sum pooling over sorted batch (reads final u from g_u0, unscales
// by 16^10 = 2^40).
// ---------------------------------------------------------------------------
__device__ __forceinline__ void pool_flush(int g, float4 acc, int lane) {
    float* p = g_pool + (size_t)g * HD + lane * 4;
    atomicAdd(p + 0, acc.x * FINAL_SCALE);
    atomicAdd(p + 1, acc.y * FINAL_SCALE);
    atomicAdd(p + 2, acc.z * FINAL_SCALE);
    atomicAdd(p + 3, acc.w * FINAL_SCALE);
}

__global__ __launch_bounds__(256) void pool_k(const int* __restrict__ batch) {
    int warp_id = (blockIdx.x * blockDim.x + threadIdx.x) >> 5;
    int lane = threadIdx.x & 31;
    int n0 = warp_id * 64;
    if (n0 >= NN) return;
    int n1 = min(n0 + 64, NN);
    float4 acc = make_float4(0.f, 0.f, 0.f, 0.f);
    int curg = batch[n0];
    for (int n = n0; n < n1; n++) {
        int g = batch[n];
        if (g != curg) {
            pool_flush(curg, acc, lane);
            acc = make_float4(0.f, 0.f, 0.f, 0.f);
            curg = g;
        }
        uint2 raw = *reinterpret_cast<const uint2*>(g_u0 + (size_t)n * HD + lane * 4);
        float2 fa = __half22float2(*reinterpret_cast<const __half2*>(&raw.x));
        float2 fb = __half22float2(*reinterpret_cast<const __half2*>(&raw.y));
        acc.x += fa.x; acc.y += fa.y; acc.z += fb.x; acc.w += fb.y;
    }
    pool_flush(curg, acc, lane);
}

// ---------------------------------------------------------------------------
// Head: y = relu(pool @ V0w + V0b) @ V1w + V1b; out = log_softmax(y)
// ---------------------------------------------------------------------------
__global__ __launch_bounds__(128) void head_k(const float* __restrict__ V0w,
                                              const float* __restrict__ V0b,
                                              const float* __restrict__ V1w,
                                              const float* __restrict__ V1b,
                                              float* __restrict__ out) {
    __shared__ float sp[HD];
    __shared__ float sz[HD];
    __shared__ float sy[OD];
    int g = blockIdx.x;
    int t = threadIdx.x;
    sp[t] = g_pool[(size_t)g * HD + t];
    __syncthreads();
    float s = V0b[t];
    #pragma unroll 8
    for (int k = 0; k < HD; k++) s = fmaf(sp[k], V0w[k * HD + t], s);
    sz[t] = fmaxf(s, 0.f);
    __syncthreads();
    if (t < OD) {
        float y = V1b[t];
        #pragma unroll 8
        for (int h = 0; h < HD; h++) y = fmaf(sz[h], V1w[h * OD + t], y);
        sy[t] = y;
    }
    __syncthreads();
    if (t == 0) {
        float m = -INFINITY;
        #pragma unroll
        for (int o = 0; o < OD; o++) m = fmaxf(m, sy[o]);
        float sum = 0.f;
        #pragma unroll
        for (int o = 0; o < OD; o++) sum += expf(sy[o] - m);
        float lse = m + logf(sum);
        #pragma unroll
        for (int o = 0; o < OD; o++) out[g * OD + o] = sy[o] - lse;
    }
}

// ---------------------------------------------------------------------------
extern "C" void kernel_launch(void* const* d_in, const int* in_sizes, int n_in,
                              void* d_out, int out_size) {
    const float* features    = (const float*)d_in[0];
    const float* edge_weight = (const float*)d_in[1];
    const float* W1  = (const float*)d_in[2];
    const float* b1  = (const float*)d_in[3];
    const float* W2  = (const float*)d_in[4];
    const float* b2  = (const float*)d_in[5];
    const float* V0w = (const float*)d_in[6];
    const float* V0b = (const float*)d_in[7];
    const float* V1w = (const float*)d_in[8];
    const float* V1b = (const float*)d_in[9];
    const int* edge_index = (const int*)d_in[10];
    const int* batch      = (const int*)d_in[11];
    float* out = (float*)d_out;

    // MLP front (fused)
    fuse_w_k<<<HD + 1, HD>>>(W1, b1, W2, b2);
    gemm_x0_k<<<(NN + 127) / 128, 256>>>(features);

    // CSR build (by dst)
    zero_k<<<(GG * HD + 255) / 256, 256>>>();
    hist_k<<<(EE + 255) / 256, 256>>>(edge_index);
    scan_k<<<1, 1024>>>();
    scatter_k<<<(EE + 255) / 256, 256>>>(edge_index, edge_weight);

    // APPNP propagation, K=10 (scaled fp16; ends in g_u0)
    int prop_blocks = (NN * 16 + 255) / 256;
    float cscale = 1.0f;   // 1/16^{it}
    for (int it = 0; it < KIT; it++) {
        cscale *= 0.0625f;                    // 1/16^{it+1}
        float coefH = ALPHA_F * cscale;
        prop_k<<<prop_blocks, 256>>>(it & 1, coefH);
    }

    // Pool + head
    int pool_warps = (NN + 63) / 64;
    pool_k<<<(pool_warps * 32 + 255) / 256, 256>>>(batch);
    head_k<<<GG, HD>>>(V0w, V0b, V1w, V1b, out);
}

// round 6
// speedup vs baseline: 1.5597x; 1.0270x over previous
#include <cuda_runtime.h>
#include <cuda_fp16.h>
#include <math.h>

#define NN 50000
#define EE 1600000
#define HD 128
#define GG 512
#define OD 10
#define KIT 10
#define ALPHA_F 0.1f
#define COEF_A (0.9f / 16.0f)        // per-step rescale by 16
#define FINAL_SCALE 1099511627776.0f // 16^10 = 2^40 (exact)

// -------- device scratch (no allocations allowed) --------
__device__ __half g_u0[(size_t)NN * HD];   // ping (scaled x)
__device__ __half g_u1[(size_t)NN * HD];   // pong
__device__ __half g_hh[(size_t)NN * HD];   // teleport term (fp16)
__device__ float  g_Wc[HD * HD];           // fused W1@W2
__device__ float  g_bc[HD];                // fused b1@W2 + b2
__device__ int    g_cnt[NN];               // in-degree histogram
__device__ int    g_rowptr[NN + 1];        // CSR row pointers (by dst)
__device__ int    g_wptr[NN];              // scatter write cursors
__device__ unsigned int g_edges[EE];       // packed: (half w)<<16 | u16 src
__device__ float  g_pool[GG * HD];         // pooled per-graph features

// ---------------------------------------------------------------------------
// Fuse the two linear layers: Wc = W1 @ W2, bc = b1 @ W2 + b2
// ---------------------------------------------------------------------------
__global__ void fuse_w_k(const float* __restrict__ W1, const float* __restrict__ b1,
                         const float* __restrict__ W2, const float* __restrict__ b2) {
    int h = threadIdx.x;
    if (blockIdx.x < HD) {
        int k = blockIdx.x;
        float s = 0.f;
        #pragma unroll 8
        for (int j = 0; j < HD; j++) s = fmaf(W1[k * HD + j], W2[j * HD + h], s);
        g_Wc[k * HD + h] = s;
    } else {
        float s = b2[h];
        #pragma unroll 8
        for (int j = 0; j < HD; j++) s = fmaf(b1[j], W2[j * HD + h], s);
        g_bc[h] = s;
    }
}

// ---------------------------------------------------------------------------
// x0[n][h] = sum_k F[k][n] * Wc[k][h] + bc[h]; writes g_u0 and g_hh (fp16).
// Tiled fp32 GEMM: block = 128 nodes x 128 dims, 256 threads, 8x8 per thread.
// ---------------------------------------------------------------------------
__global__ __launch_bounds__(256) void gemm_x0_k(const float* __restrict__ F) {
    __shared__ float sF[32][HD + 4];
    __shared__ float sW[32][HD];
    int n0 = blockIdx.x * 128;
    int tx = threadIdx.x & 15;   // dim group
    int ty = threadIdx.x >> 4;   // node group
    float acc[8][8];
    #pragma unroll
    for (int i = 0; i < 8; i++)
        #pragma unroll
        for (int j = 0; j < 8; j++) acc[i][j] = 0.f;

    for (int kt = 0; kt < HD; kt += 32) {
        for (int i = threadIdx.x; i < 32 * 128; i += 256) {
            int kk = i >> 7, c = i & 127;
            int n = n0 + c;
            sF[kk][c] = (n < NN) ? F[(size_t)(kt + kk) * NN + n] : 0.f;
            sW[kk][c] = g_Wc[(kt + kk) * HD + c];
        }
        __syncthreads();
        #pragma unroll
        for (int kk = 0; kk < 32; kk++) {
            float a[8], b[8];
            #pragma unroll
            for (int i = 0; i < 8; i++) a[i] = sF[kk][ty * 8 + i];
            #pragma unroll
            for (int j = 0; j < 8; j++) b[j] = sW[kk][tx * 8 + j];
            #pragma unroll
            for (int i = 0; i < 8; i++)
                #pragma unroll
                for (int j = 0; j < 8; j++) acc[i][j] = fmaf(a[i], b[j], acc[i][j]);
        }
        __syncthreads();
    }
    #pragma unroll
    for (int i = 0; i < 8; i++) {
        int n = n0 + ty * 8 + i;
        if (n < NN) {
            __align__(16) __half hb[8];
            #pragma unroll
            for (int j = 0; j < 8; j++) {
                float v = acc[i][j] + g_bc[tx * 8 + j];
                hb[j] = __float2half_rn(v);
            }
            uint4 pk = *reinterpret_cast<uint4*>(hb);
            *reinterpret_cast<uint4*>(&g_u0[(size_t)n * HD + tx * 8]) = pk;
            *reinterpret_cast<uint4*>(&g_hh[(size_t)n * HD + tx * 8]) = pk;
        }
    }
}

// ---------------------------------------------------------------------------
// Zero histogram + pool buffer
// ---------------------------------------------------------------------------
__global__ void zero_k() {
    int i = blockIdx.x * blockDim.x + threadIdx.x;
    if (i < NN) g_cnt[i] = 0;
    if (i < GG * HD) g_pool[i] = 0.f;
}

// ---------------------------------------------------------------------------
// In-degree histogram over dst
// ---------------------------------------------------------------------------
__global__ void hist_k(const int* __restrict__ ei) {
    int e = blockIdx.x * blockDim.x + threadIdx.x;
    if (e < EE) atomicAdd(&g_cnt[ei[EE + e]], 1);
}

// ---------------------------------------------------------------------------
// Exclusive scan of g_cnt -> g_rowptr / g_wptr. Single block, 1024 threads,
// warp-shuffle scan.
// ---------------------------------------------------------------------------
__global__ __launch_bounds__(1024) void scan_k() {
    __shared__ int wsum[32];
    __shared__ int carry_sh;
    int t = threadIdx.x;
    int lane = t & 31;
    int wid = t >> 5;
    if (t == 0) { carry_sh = 0; g_rowptr[0] = 0; }
    __syncthreads();
    for (int base = 0; base < NN; base += 1024) {
        int idx = base + t;
        int c = (idx < NN) ? g_cnt[idx] : 0;
        int v = c;
        #pragma unroll
        for (int off = 1; off < 32; off <<= 1) {
            int u = __shfl_up_sync(0xffffffffu, v, off);
            if (lane >= off) v += u;
        }
        if (lane == 31) wsum[wid] = v;
        __syncthreads();
        if (wid == 0) {
            int s = wsum[lane];
            #pragma unroll
            for (int off = 1; off < 32; off <<= 1) {
                int u = __shfl_up_sync(0xffffffffu, s, off);
                if (lane >= off) s += u;
            }
            wsum[lane] = s;
        }
        __syncthreads();
        int incl = v + (wid ? wsum[wid - 1] : 0);
        int chunk_total = wsum[31];
        int carry = carry_sh;
        if (idx < NN) {
            g_rowptr[idx + 1] = carry + incl;
            g_wptr[idx]       = carry + incl - c;
        }
        __syncthreads();
        if (t == 0) carry_sh = carry + chunk_total;
        __syncthreads();
    }
}

// ---------------------------------------------------------------------------
// Scatter edges into CSR order (by dst); packed record (half w)<<16 | u16 src
// ---------------------------------------------------------------------------
__global__ void scatter_k(const int* __restrict__ ei, const float* __restrict__ ew) {
    int e = blockIdx.x * blockDim.x + threadIdx.x;
    if (e < EE) {
        int d = ei[EE + e];
        int pos = atomicAdd(&g_wptr[d], 1);
        unsigned short wb = __half_as_ushort(__float2half_rn(ew[e]));
        g_edges[pos] = ((unsigned int)wb << 16) | (unsigned int)(ei[e] & 0xFFFF);
    }
}

// ---------------------------------------------------------------------------
// One scaled APPNP step:
//   u_out[d] = (0.9/16) * sum_e w_e * u_in[src_e] + (0.1/16^{k+1}) * h[d]
// HALF-WARP per dst node: 16 lanes x uint4(16B) cover the 256B fp16 row.
// 4-edge unrolled mainloop: 4 records + 4 independent row gathers in flight.
// ---------------------------------------------------------------------------
__device__ __forceinline__ void edge_fma(unsigned int rec, const uint4* xin, int sub,
                                         float2& a0, float2& a1, float2& a2, float2& a3) {
    int src = (int)(rec & 0xFFFFu);
    float w = __half2float(__ushort_as_half((unsigned short)(rec >> 16)));
    uint4 raw = xin[src * 16 + sub];
    float2 p0 = __half22float2(*reinterpret_cast<const __half2*>(&raw.x));
    float2 p1 = __half22float2(*reinterpret_cast<const __half2*>(&raw.y));
    float2 p2 = __half22float2(*reinterpret_cast<const __half2*>(&raw.z));
    float2 p3 = __half22float2(*reinterpret_cast<const __half2*>(&raw.w));
    a0.x = fmaf(w, p0.x, a0.x); a0.y = fmaf(w, p0.y, a0.y);
    a1.x = fmaf(w, p1.x, a1.x); a1.y = fmaf(w, p1.y, a1.y);
    a2.x = fmaf(w, p2.x, a2.x); a2.y = fmaf(w, p2.y, a2.y);
    a3.x = fmaf(w, p3.x, a3.x); a3.y = fmaf(w, p3.y, a3.y);
}

__global__ __launch_bounds__(256) void prop_k(int flip, float coefH) {
    const uint4* __restrict__ xin =
        reinterpret_cast<const uint4*>(flip ? g_u1 : g_u0);
    uint4* __restrict__ xout =
        reinterpret_cast<uint4*>(flip ? g_u0 : g_u1);
    int node = (blockIdx.x * blockDim.x + threadIdx.x) >> 4;  // half-warp id
    int sub = threadIdx.x & 15;
    if (node >= NN) return;
    int beg = g_rowptr[node];
    int end = g_rowptr[node + 1];
    float2 a0 = make_float2(0.f, 0.f), a1 = a0, a2 = a0, a3 = a0;

    int j = beg;
    for (; j + 4 <= end; j += 4) {
        unsigned int r0 = g_edges[j + 0];
        unsigned int r1 = g_edges[j + 1];
        unsigned int r2 = g_edges[j + 2];
        unsigned int r3 = g_edges[j + 3];
        // 4 independent gathers; compiler front-batches the LDG.128s
        int s0 = (int)(r0 & 0xFFFFu), s1 = (int)(r1 & 0xFFFFu);
        int s2 = (int)(r2 & 0xFFFFu), s3 = (int)(r3 & 0xFFFFu);
        uint4 q0 = xin[s0 * 16 + sub];
        uint4 q1 = xin[s1 * 16 + sub];
        uint4 q2 = xin[s2 * 16 + sub];
        uint4 q3 = xin[s3 * 16 + sub];
        float w0 = __half2float(__ushort_as_half((unsigned short)(r0 >> 16)));
        float w1 = __half2float(__ushort_as_half((unsigned short)(r1 >> 16)));
        float w2 = __half2float(__ushort_as_half((unsigned short)(r2 >> 16)));
        float w3 = __half2float(__ushort_as_half((unsigned short)(r3 >> 16)));
        {
            float2 p0 = __half22float2(*reinterpret_cast<const __half2*>(&q0.x));
            float2 p1 = __half22float2(*reinterpret_cast<const __half2*>(&q0.y));
            float2 p2 = __half22float2(*reinterpret_cast<const __half2*>(&q0.z));
            float2 p3 = __half22float2(*reinterpret_cast<const __half2*>(&q0.w));
            a0.x = fmaf(w0, p0.x, a0.x); a0.y = fmaf(w0, p0.y, a0.y);
            a1.x = fmaf(w0, p1.x, a1.x); a1.y = fmaf(w0, p1.y, a1.y);
            a2.x = fmaf(w0, p2.x, a2.x); a2.y = fmaf(w0, p2.y, a2.y);
            a3.x = fmaf(w0, p3.x, a3.x); a3.y = fmaf(w0, p3.y, a3.y);
        }
        {
            float2 p0 = __half22float2(*reinterpret_cast<const __half2*>(&q1.x));
            float2 p1 = __half22float2(*reinterpret_cast<const __half2*>(&q1.y));
            float2 p2 = __half22float2(*reinterpret_cast<const __half2*>(&q1.z));
            float2 p3 = __half22float2(*reinterpret_cast<const __half2*>(&q1.w));
            a0.x = fmaf(w1, p0.x, a0.x); a0.y = fmaf(w1, p0.y, a0.y);
            a1.x = fmaf(w1, p1.x, a1.x); a1.y = fmaf(w1, p1.y, a1.y);
            a2.x = fmaf(w1, p2.x, a2.x); a2.y = fmaf(w1, p2.y, a2.y);
            a3.x = fmaf(w1, p3.x, a3.x); a3.y = fmaf(w1, p3.y, a3.y);
        }
        {
            float2 p0 = __half22float2(*reinterpret_cast<const __half2*>(&q2.x));
            float2 p1 = __half22float2(*reinterpret_cast<const __half2*>(&q2.y));
            float2 p2 = __half22float2(*reinterpret_cast<const __half2*>(&q2.z));
            float2 p3 = __half22float2(*reinterpret_cast<const __half2*>(&q2.w));
            a0.x = fmaf(w2, p0.x, a0.x); a0.y = fmaf(w2, p0.y, a0.y);
            a1.x = fmaf(w2, p1.x, a1.x); a1.y = fmaf(w2, p1.y, a1.y);
            a2.x = fmaf(w2, p2.x, a2.x); a2.y = fmaf(w2, p2.y, a2.y);
            a3.x = fmaf(w2, p3.x, a3.x); a3.y = fmaf(w2, p3.y, a3.y);
        }
        {
            float2 p0 = __half22float2(*reinterpret_cast<const __half2*>(&q3.x));
            float2 p1 = __half22float2(*reinterpret_cast<const __half2*>(&q3.y));
            float2 p2 = __half22float2(*reinterpret_cast<const __half2*>(&q3.z));
            float2 p3 = __half22float2(*reinterpret_cast<const __half2*>(&q3.w));
            a0.x = fmaf(w3, p0.x, a0.x); a0.y = fmaf(w3, p0.y, a0.y);
            a1.x = fmaf(w3, p1.x, a1.x); a1.y = fmaf(w3, p1.y, a1.y);
            a2.x = fmaf(w3, p2.x, a2.x); a2.y = fmaf(w3, p2.y, a2.y);
            a3.x = fmaf(w3, p3.x, a3.x); a3.y = fmaf(w3, p3.y, a3.y);
        }
    }
    #pragma unroll 1
    for (; j < end; j++) {
        edge_fma(g_edges[j], xin, sub, a0, a1, a2, a3);
    }

    uint4 hraw = reinterpret_cast<const uint4*>(g_hh)[node * 16 + sub];
    float2 h0 = __half22float2(*reinterpret_cast<const __half2*>(&hraw.x));
    float2 h1 = __half22float2(*reinterpret_cast<const __half2*>(&hraw.y));
    float2 h2 = __half22float2(*reinterpret_cast<const __half2*>(&hraw.z));
    float2 h3 = __half22float2(*reinterpret_cast<const __half2*>(&hraw.w));
    float2 o0, o1, o2, o3;
    o0.x = fmaf(COEF_A, a0.x, coefH * h0.x); o0.y = fmaf(COEF_A, a0.y, coefH * h0.y);
    o1.x = fmaf(COEF_A, a1.x, coefH * h1.x); o1.y = fmaf(COEF_A, a1.y, coefH * h1.y);
    o2.x = fmaf(COEF_A, a2.x, coefH * h2.x); o2.y = fmaf(COEF_A, a2.y, coefH * h2.y);
    o3.x = fmaf(COEF_A, a3.x, coefH * h3.x); o3.y = fmaf(COEF_A, a3.y, coefH * h3.y);
    uint4 outw;
    *reinterpret_cast<__half2*>(&outw.x) = __float22half2_rn(o0);
    *reinterpret_cast<__half2*>(&outw.y) = __float22half2_rn(o1);
    *reinterpret_cast<__half2*>(&outw.z) = __float22half2_rn(o2);
    *reinterpret_cast<__half2*>(&outw.w) = __float22half2_rn(o3);
    xout[node * 16 + sub] = outw;
}

// ---------------------------------------------------------------------------
// Segment-sum pooling over sorted batch (reads final u from g_u0, unscales
// by 16^10 = 2^40).
// ---------------------------------------------------------------------------
__device__ __forceinline__ void pool_flush(int g, float4 acc, int lane) {
    float* p = g_pool + (size_t)g * HD + lane * 4;
    atomicAdd(p + 0, acc.x * FINAL_SCALE);
    atomicAdd(p + 1, acc.y * FINAL_SCALE);
    atomicAdd(p + 2, acc.z * FINAL_SCALE);
    atomicAdd(p + 3, acc.w * FINAL_SCALE);
}

__global__ __launch_bounds__(256) void pool_k(const int* __restrict__ batch) {
    int warp_id = (blockIdx.x * blockDim.x + threadIdx.x) >> 5;
    int lane = threadIdx.x & 31;
    int n0 = warp_id * 64;
    if (n0 >= NN) return;
    int n1 = min(n0 + 64, NN);
    float4 acc = make_float4(0.f, 0.f, 0.f, 0.f);
    int curg = batch[n0];
    for (int n = n0; n < n1; n++) {
        int g = batch[n];
        if (g != curg) {
            pool_flush(curg, acc, lane);
            acc = make_float4(0.f, 0.f, 0.f, 0.f);
            curg = g;
        }
        uint2 raw = *reinterpret_cast<const uint2*>(g_u0 + (size_t)n * HD + lane * 4);
        float2 fa = __half22float2(*reinterpret_cast<const __half2*>(&raw.x));
        float2 fb = __half22float2(*reinterpret_cast<const __half2*>(&raw.y));
        acc.x += fa.x; acc.y += fa.y; acc.z += fb.x; acc.w += fb.y;
    }
    pool_flush(curg, acc, lane);
}

// ---------------------------------------------------------------------------
// Head: y = relu(pool @ V0w + V0b) @ V1w + V1b; out = log_softmax(y)
// ---------------------------------------------------------------------------
__global__ __launch_bounds__(128) void head_k(const float* __restrict__ V0w,
                                              const float* __restrict__ V0b,
                                              const float* __restrict__ V1w,
                                              const float* __restrict__ V1b,
                                              float* __restrict__ out) {
    __shared__ float sp[HD];
    __shared__ float sz[HD];
    __shared__ float sy[OD];
    int g = blockIdx.x;
    int t = threadIdx.x;
    sp[t] = g_pool[(size_t)g * HD + t];
    __syncthreads();
    float s = V0b[t];
    #pragma unroll 8
    for (int k = 0; k < HD; k++) s = fmaf(sp[k], V0w[k * HD + t], s);
    sz[t] = fmaxf(s, 0.f);
    __syncthreads();
    if (t < OD) {
        float y = V1b[t];
        #pragma unroll 8
        for (int h = 0; h < HD; h++) y = fmaf(sz[h], V1w[h * OD + t], y);
        sy[t] = y;
    }
    __syncthreads();
    if (t == 0) {
        float m = -INFINITY;
        #pragma unroll
        for (int o = 0; o < OD; o++) m = fmaxf(m, sy[o]);
        float sum = 0.f;
        #pragma unroll
        for (int o = 0; o < OD; o++) sum += expf(sy[o] - m);
        float lse = m + logf(sum);
        #pragma unroll
        for (int o = 0; o < OD; o++) out[g * OD + o] = sy[o] - lse;
    }
}

// ---------------------------------------------------------------------------
extern "C" void kernel_launch(void* const* d_in, const int* in_sizes, int n_in,
                              void* d_out, int out_size) {
    const float* features    = (const float*)d_in[0];
    const float* edge_weight = (const float*)d_in[1];
    const float* W1  = (const float*)d_in[2];
    const float* b1  = (const float*)d_in[3];
    const float* W2  = (const float*)d_in[4];
    const float* b2  = (const float*)d_in[5];
    const float* V0w = (const float*)d_in[6];
    const float* V0b = (const float*)d_in[7];
    const float* V1w = (const float*)d_in[8];
    const float* V1b = (const float*)d_in[9];
    const int* edge_index = (const int*)d_in[10];
    const int* batch      = (const int*)d_in[11];
    float* out = (float*)d_out;

    // MLP front (fused)
    fuse_w_k<<<HD + 1, HD>>>(W1, b1, W2, b2);
    gemm_x0_k<<<(NN + 127) / 128, 256>>>(features);

    // CSR build (by dst)
    zero_k<<<(GG * HD + 255) / 256, 256>>>();
    hist_k<<<(EE + 255) / 256, 256>>>(edge_index);
    scan_k<<<1, 1024>>>();
    scatter_k<<<(EE + 255) / 256, 256>>>(edge_index, edge_weight);

    // APPNP propagation, K=10 (scaled fp16; ends in g_u0)
    int prop_blocks = (NN * 16 + 255) / 256;
    float cscale = 1.0f;   // 1/16^{it}
    for (int it = 0; it < KIT; it++) {
        cscale *= 0.0625f;                    // 1/16^{it+1}
        float coefH = ALPHA_F * cscale;
        prop_k<<<prop_blocks, 256>>>(it & 1, coefH);
    }

    // Pool + head
    int pool_warps = (NN + 63) / 64;
    pool_k<<<(pool_warps * 32 + 255) / 256, 256>>>(batch);
    head_k<<<GG, HD>>>(V0w, V0b, V1w, V1b, out);
}